// round 8
// baseline (speedup 1.0000x reference)
#include <cuda_runtime.h>
#include <math.h>

#define BB 128
#define SS 256
#define HH 512

typedef unsigned long long u64;

// ---------------- device scratch (no allocations allowed) -------------------
__device__ float g_rsWr[HH];            // rowsum(Wr)
__device__ float g_rsW[HH];             // rowsum(W)
__device__ float g_part[4][BB * SS];    // per-jblock logit partials
__device__ float g_Gt[SS * BB];         // softmax gates, (s, b)
__device__ float g_C[2][HH * BB];       // recurrent state, transposed (h, b)
__device__ unsigned g_flags2[8][16];    // per-(bg,hg) step counters (zeroed by softmax)

// ---------------- f32x2 helpers ----------------------------------------------
__device__ __forceinline__ u64 pk2(float x, float y) {
    u64 r;
    asm("mov.b64 %0, {%1,%2};" : "=l"(r) : "f"(x), "f"(y));
    return r;
}
__device__ __forceinline__ void upk2(u64 v, float& x, float& y) {
    asm("mov.b64 {%0,%1}, %2;" : "=f"(x), "=f"(y) : "l"(v));
}
__device__ __forceinline__ u64 fma2_(u64 a, u64 b, u64 c) {
    u64 d;
    asm("fma.rn.f32x2 %0, %1, %2, %3;" : "=l"(d) : "l"(a), "l"(b), "l"(c));
    return d;
}
__device__ __forceinline__ u64 add2_(u64 a, u64 b) {
    u64 d;
    asm("add.rn.f32x2 %0, %1, %2;" : "=l"(d) : "l"(a), "l"(b));
    return d;
}
__device__ __forceinline__ float tanh_approx(float x) {
    float y;
    asm("tanh.approx.f32 %0, %1;" : "=f"(y) : "f"(x));
    return y;
}
__device__ __forceinline__ unsigned ld_acq(const unsigned* p) {
    unsigned v;
    asm volatile("ld.acquire.gpu.global.u32 %0, [%1];" : "=r"(v) : "l"(p));
    return v;
}
__device__ __forceinline__ void st_rel(unsigned* p, unsigned v) {
    asm volatile("st.release.gpu.global.u32 [%0], %1;" :: "l"(p), "r"(v) : "memory");
}

// ---------------- prep: rowsums of Wr and W ----------------------------------
__global__ void prep_kernel(const float* __restrict__ Wr, const float* __restrict__ W)
{
    int warp = threadIdx.x >> 5, lane = threadIdx.x & 31;
    int rowId = blockIdx.x * 8 + warp;               // 0..1023
    const float* src = (rowId < HH) ? Wr : W;
    int h = rowId & (HH - 1);
    const float4* s4 = reinterpret_cast<const float4*>(src + (size_t)h * HH);
    float s = 0.f;
    for (int i = lane; i < HH / 4; i += 32) {
        float4 v = s4[i];
        s += (v.x + v.y) + (v.z + v.w);
    }
#pragma unroll
    for (int o = 16; o > 0; o >>= 1) s += __shfl_xor_sync(0xffffffffu, s, o);
    if (lane == 0) {
        if (rowId < HH) g_rsWr[h] = s;
        else            g_rsW[h]  = s;
    }
}

// ---------------- gate MLP: fused z-build + GEMM (f32x2, 8x8) + tanh + dot ---
// grid (S/128, 512/128, B), 256 threads. 128x128 tile, K=2048 built on the fly.
// Bs double-buffered with register prefetch: 1 sync per B-tile.
__global__ void __launch_bounds__(256, 2) gate_kernel(
    const float* __restrict__ facts, const float* __restrict__ q,
    const float* __restrict__ m, const float* __restrict__ z1w,
    const float* __restrict__ z1b, const float* __restrict__ z2w)
{
    __shared__ float qs[HH], ms[HH];
    __shared__ float As[4][16][132];   // padded rows: kill STS conflicts
    __shared__ float Bs[2][16][128];   // double buffer

    int tid = threadIdx.x;
    int b  = blockIdx.z;
    int s0 = blockIdx.x * 128;
    int j0 = blockIdx.y * 128;

    for (int i = tid; i < HH; i += 256) {
        qs[i] = q[b * HH + i];
        ms[i] = m[b * HH + i];
    }

    const float* fb = facts + ((size_t)b * SS + s0) * HH;

    // A-build fixed sub-indices: element r -> (ss, kk) within a 128x16 k-tile
    int a_ss[8], a_kk[8];
#pragma unroll
    for (int r = 0; r < 8; r++) { int i = tid + r * 256; a_ss[r] = i >> 4; a_kk[r] = i & 15; }

    // facts prefetch for k-tile 0
    float freg[8];
#pragma unroll
    for (int r = 0; r < 8; r++) freg[r] = fb[(size_t)a_ss[r] * HH + a_kk[r]];

    // B prefetch: tile t -> z1w rows [ (t&3)*HH + (t>>2)*16 , +16 ), cols j0..+128
    // thread loads 2 float4: f4 index i in {tid, tid+256}: kk=i>>5, jj=(i&31)*4
    float4 breg[2];
    {
        int kr = ((0 & 3) * HH) + ((0 >> 2) * 16);
#pragma unroll
        for (int r = 0; r < 2; r++) {
            int i = tid + r * 256; int kk = i >> 5, jj = (i & 31) * 4;
            breg[r] = *reinterpret_cast<const float4*>(
                &z1w[(size_t)(kr + kk) * HH + j0 + jj]);
        }
    }

    int tx = tid & 15, ty = tid >> 4;     // tx: 8 j's, ty: 8 s's
    u64 acc2[4][8];                        // [s-pair][j]
#pragma unroll
    for (int i = 0; i < 4; i++)
#pragma unroll
        for (int j = 0; j < 8; j++) acc2[i][j] = 0ull;

    __syncthreads();     // qs/ms visible for As builds
    // store B tile 0, prefetch tile 1
    {
#pragma unroll
        for (int r = 0; r < 2; r++) {
            int i = tid + r * 256; int kk = i >> 5, jj = (i & 31) * 4;
            *reinterpret_cast<float4*>(&Bs[0][kk][jj]) = breg[r];
        }
        int kr = ((1 & 3) * HH) + ((1 >> 2) * 16);
#pragma unroll
        for (int r = 0; r < 2; r++) {
            int i = tid + r * 256; int kk = i >> 5, jj = (i & 31) * 4;
            breg[r] = *reinterpret_cast<const float4*>(
                &z1w[(size_t)(kr + kk) * HH + j0 + jj]);
        }
    }

    for (int t = 0; t < 128; t++) {
        int blk = t & 3;
        __syncthreads();   // Bs[t&1] visible; compute t-1 done (As/other buf free)
        if (blk == 0) {
            int k0 = (t >> 2) * 16;
#pragma unroll
            for (int r = 0; r < 8; r++) {
                float fv = freg[r];
                int kk = k0 + a_kk[r];
                float qv = qs[kk], mv = ms[kk];
                As[0][a_kk[r]][a_ss[r]] = fv * qv;
                As[1][a_kk[r]][a_ss[r]] = fv * mv;
                As[2][a_kk[r]][a_ss[r]] = fabsf(fv - qv);
                As[3][a_kk[r]][a_ss[r]] = fabsf(fv - mv);
            }
            if (t + 4 < 128) {
                int k0n = k0 + 16;
#pragma unroll
                for (int r = 0; r < 8; r++)
                    freg[r] = fb[(size_t)a_ss[r] * HH + k0n + a_kk[r]];
            }
            __syncthreads();   // As ready
        }

        // compute tile t
        const float (*Bc)[128] = Bs[t & 1];
#pragma unroll
        for (int kk = 0; kk < 16; kk++) {
            ulonglong2 a01 = *reinterpret_cast<const ulonglong2*>(&As[blk][kk][ty * 8]);
            ulonglong2 a23 = *reinterpret_cast<const ulonglong2*>(&As[blk][kk][ty * 8 + 4]);
            float4 bv0 = *reinterpret_cast<const float4*>(&Bc[kk][tx * 8]);
            float4 bv1 = *reinterpret_cast<const float4*>(&Bc[kk][tx * 8 + 4]);
            u64 ap[4] = {a01.x, a01.y, a23.x, a23.y};
            float bf[8] = {bv0.x, bv0.y, bv0.z, bv0.w, bv1.x, bv1.y, bv1.z, bv1.w};
#pragma unroll
            for (int j = 0; j < 8; j++) {
                u64 bd = pk2(bf[j], bf[j]);
#pragma unroll
                for (int i = 0; i < 4; i++)
                    acc2[i][j] = fma2_(ap[i], bd, acc2[i][j]);
            }
        }

        // stage next tile: STS t+1 (other buffer), prefetch t+2
        if (t < 127) {
#pragma unroll
            for (int r = 0; r < 2; r++) {
                int i = tid + r * 256; int kk = i >> 5, jj = (i & 31) * 4;
                *reinterpret_cast<float4*>(&Bs[(t + 1) & 1][kk][jj]) = breg[r];
            }
            if (t < 126) {
                int tn = t + 2;
                int kr = ((tn & 3) * HH) + ((tn >> 2) * 16);
#pragma unroll
                for (int r = 0; r < 2; r++) {
                    int i = tid + r * 256; int kk = i >> 5, jj = (i & 31) * 4;
                    breg[r] = *reinterpret_cast<const float4*>(
                        &z1w[(size_t)(kr + kk) * HH + j0 + jj]);
                }
            }
        }
    }

    // epilogue: tanh (approx), dot with z2_w, reduce over the 128 j's
    float z1bv[8], z2wv[8];
#pragma unroll
    for (int j = 0; j < 8; j++) {
        int jc = j0 + tx * 8 + j;
        z1bv[j] = z1b[jc];
        z2wv[j] = z2w[jc];
    }
    float p[8];
#pragma unroll
    for (int i = 0; i < 8; i++) p[i] = 0.f;
#pragma unroll
    for (int ip = 0; ip < 4; ip++) {
#pragma unroll
        for (int j = 0; j < 8; j++) {
            float lo, hi;
            upk2(acc2[ip][j], lo, hi);
            p[ip * 2 + 0] = fmaf(tanh_approx(lo + z1bv[j]), z2wv[j], p[ip * 2 + 0]);
            p[ip * 2 + 1] = fmaf(tanh_approx(hi + z1bv[j]), z2wv[j], p[ip * 2 + 1]);
        }
    }
#pragma unroll
    for (int i = 0; i < 8; i++) {
#pragma unroll
        for (int o = 8; o > 0; o >>= 1)
            p[i] += __shfl_xor_sync(0xffffffffu, p[i], o);
    }
    if (tx == 0) {
#pragma unroll
        for (int i = 0; i < 8; i++)
            g_part[blockIdx.y][b * SS + s0 + ty * 8 + i] = p[i];
    }
}

// ---------------- softmax over S per batch (also zeroes scan flags) -----------
__global__ void softmax_kernel()
{
    int b = blockIdx.x, s = threadIdx.x;   // 256 threads
    if (b == 0 && s < 128) g_flags2[s >> 4][s & 15] = 0u;  // stream-ordered before scan
    float l = 0.f;
#pragma unroll
    for (int jb = 0; jb < 4; jb++) l += g_part[jb][b * SS + s];
    __shared__ float sm[256];
    sm[s] = l;
    __syncthreads();
#pragma unroll
    for (int o = 128; o > 0; o >>= 1) {
        if (s < o) sm[s] = fmaxf(sm[s], sm[s + o]);
        __syncthreads();
    }
    float mx = sm[0];
    __syncthreads();
    float e = expf(l - mx);
    sm[s] = e;
    __syncthreads();
#pragma unroll
    for (int o = 128; o > 0; o >>= 1) {
        if (s < o) sm[s] += sm[s + o];
        __syncthreads();
    }
    g_Gt[s * BB + b] = e / sm[0];
}

// ---------------- persistent scan: 128 blocks = 16 hg x 8 bg ------------------
// Block owns 32 h x 16 b. (R,U)-paired weights persist in smem (128KB).
// Per step: hoisted facts/G loads -> vector flag poll (no atomics) ->
// pipelined L2 C reads + FMA -> one smem reduce -> fused epilogue.
__global__ void __launch_bounds__(512, 1) scan_persist(
    const float* __restrict__ facts,
    const float* __restrict__ Ur, const float* __restrict__ U,
    const float* __restrict__ br, const float* __restrict__ bur,
    const float* __restrict__ bw, const float* __restrict__ bu)
{
    extern __shared__ __align__(16) char dsm[];
    u64* wpk = reinterpret_cast<u64*>(dsm);            // [512][32]: pk2(Ur, U)
    u64* red = reinterpret_cast<u64*>(dsm + 131072);   // [16][16][33] padded

    __shared__ float hcs[5][32];

    int tid = threadIdx.x;
    int hg = blockIdx.x >> 3;      // 0..15
    int bg = blockIdx.x & 7;       // 0..7
    int h0 = hg * 32;
    int b0 = bg * 16;

    // one-time: pack (R,U) weight pairs for this h-slice
    for (int idx = tid; idx < 512 * 32; idx += 512) {
        int k = idx >> 5, h = idx & 31;
        wpk[idx] = pk2(Ur[(size_t)k * HH + h0 + h], U[(size_t)k * HH + h0 + h]);
    }
    if (tid < 32) {
        int h = h0 + tid;
        hcs[0][tid] = g_rsWr[h];
        hcs[1][tid] = br[h] + bur[h];
        hcs[2][tid] = g_rsW[h];
        hcs[3][tid] = bw[h];
        hcs[4][tid] = bu[h];
    }
    __syncthreads();

    // compute mapping
    int ks = tid >> 5;
    int lane = tid & 31;
    int hq = lane >> 2, bq = lane & 3;

    // reduce/epilogue mapping: one (h,b) per thread, fixed across steps
    int ep_pos = tid >> 4, ep_i = tid & 15;
    int e_hq = ep_pos >> 2, e_bq = ep_pos & 3;
    int e_hh = ep_i & 3,   e_bb = ep_i >> 2;        // hh fastest -> coalesced facts
    int ehl = e_hq * 4 + e_hh;                      // local h
    int eh  = h0 + ehl;
    int eb  = b0 + e_bq * 4 + e_bb;
    float cur_c = 0.f;

    const int CSTRIDE = BB / 4;

    for (int s = 0; s < SS; s++) {
        // hoisted epilogue inputs (independent of C)
        float fv = __ldg(facts + ((size_t)eb * SS + s) * HH + eh);
        float gt = __ldg(g_Gt + s * BB + eb);

        u64 aRU = 0ull;

        if (s > 0) {
            // vector flag poll: all 16 hg producers of this bg at step >= s
            {
                unsigned mine = (lane < 16) ? ld_acq(&g_flags2[bg][lane]) : 0xffffffffu;
                while (__any_sync(0xffffffffu, mine < (unsigned)s)) {
                    mine = (lane < 16) ? ld_acq(&g_flags2[bg][lane]) : 0xffffffffu;
                }
            }

            const float* __restrict__ Cin = g_C[s & 1];
            u64 acc[4][4];
#pragma unroll
            for (int i = 0; i < 4; i++)
#pragma unroll
                for (int j = 0; j < 4; j++) acc[i][j] = 0ull;

            const float4* cp = reinterpret_cast<const float4*>(
                Cin + (size_t)(ks * 32) * BB + b0 + bq * 4);

            // software-pipelined C loads: 4-deep prefetch
            float4 cbuf[4];
#pragma unroll
            for (int p = 0; p < 4; p++) cbuf[p] = __ldcg(cp + (size_t)p * CSTRIDE);
#pragma unroll
            for (int g8 = 0; g8 < 8; g8++) {
                float4 cur[4];
#pragma unroll
                for (int p = 0; p < 4; p++) cur[p] = cbuf[p];
                if (g8 < 7) {
#pragma unroll
                    for (int p = 0; p < 4; p++)
                        cbuf[p] = __ldcg(cp + (size_t)((g8 + 1) * 4 + p) * CSTRIDE);
                }
#pragma unroll
                for (int kk4 = 0; kk4 < 4; kk4++) {
                    int kk = g8 * 4 + kk4;
                    float4 cv = cur[kk4];
                    u64 cd[4] = {pk2(cv.x, cv.x), pk2(cv.y, cv.y),
                                 pk2(cv.z, cv.z), pk2(cv.w, cv.w)};
                    const u64* wr = &wpk[(ks * 32 + kk) * 32 + hq * 4];
                    ulonglong2 w01 = *reinterpret_cast<const ulonglong2*>(wr);
                    ulonglong2 w23 = *reinterpret_cast<const ulonglong2*>(wr + 2);
                    u64 w[4] = {w01.x, w01.y, w23.x, w23.y};
#pragma unroll
                    for (int hh = 0; hh < 4; hh++)
#pragma unroll
                        for (int bb = 0; bb < 4; bb++)
                            acc[hh][bb] = fma2_(cd[bb], w[hh], acc[hh][bb]);
                }
            }

            // write k-split partials (prev step's red reads sealed by last sync)
#pragma unroll
            for (int hh = 0; hh < 4; hh++)
#pragma unroll
                for (int bb = 0; bb < 4; bb++) {
                    int i = bb * 4 + hh;
                    red[(size_t)(ks * 16 + i) * 33 + lane] = acc[hh][bb];
                }
            __syncthreads();

            // each thread sums its 16 k-split partials for its own (h,b)
            u64 v = red[(size_t)ep_i * 33 + ep_pos];
#pragma unroll
            for (int t = 1; t < 16; t++)
                v = add2_(v, red[(size_t)(t * 16 + ep_i) * 33 + ep_pos]);
            aRU = v;
        }

        // fused epilogue: nonlinearity + blend; C kept in a register
        {
            float aR, aU;
            upk2(aRU, aR, aU);
            float* __restrict__ Cout = g_C[(s + 1) & 1];
            float rr = 1.f / (1.f + expf(-(fmaf(fv, hcs[0][ehl], hcs[1][ehl]) + aR)));
            float ht = tanhf(fmaf(rr, aU + hcs[4][ehl],
                                  fmaf(fv, hcs[2][ehl], hcs[3][ehl])));
            cur_c = fmaf(gt, ht - cur_c, cur_c);
            Cout[(size_t)eh * BB + eb] = cur_c;
        }
        __threadfence();       // make C stores globally visible
        __syncthreads();       // all stores + fences in this block done
        if (tid == 0) st_rel(&g_flags2[bg][hg], (unsigned)(s + 1));
    }
}

// ---------------- final: relu(concat @ nm_w + nm_b) ---------------------------
__global__ void __launch_bounds__(512) final_kernel(
    const float* __restrict__ prevM, const float* __restrict__ q,
    const float* __restrict__ nm_w, const float* __restrict__ nm_b,
    float* __restrict__ out)
{
    __shared__ float cs[3 * HH];
    int b = blockIdx.x, tid = threadIdx.x;    // 512 threads
    cs[tid]          = prevM[b * HH + tid];
    cs[HH + tid]     = g_C[0][(size_t)tid * BB + b];   // final C lives in buffer 0
    cs[2 * HH + tid] = q[b * HH + tid];
    __syncthreads();
    float acc = nm_b[tid];
#pragma unroll 8
    for (int k = 0; k < 3 * HH; k++)
        acc = fmaf(cs[k], nm_w[(size_t)k * HH + tid], acc);
    out[b * HH + tid] = fmaxf(acc, 0.f);
}

// ---------------- launch -------------------------------------------------------
extern "C" void kernel_launch(void* const* d_in, const int* in_sizes, int n_in,
                              void* d_out, int out_size)
{
    const float* facts     = (const float*)d_in[0];
    const float* questions = (const float*)d_in[1];
    const float* prevM     = (const float*)d_in[2];
    const float* z1_w      = (const float*)d_in[3];
    const float* z1_b      = (const float*)d_in[4];
    const float* z2_w      = (const float*)d_in[5];
    // d_in[6] z2_b: constant shift, softmax-invariant — unused
    const float* Wr        = (const float*)d_in[7];
    const float* br        = (const float*)d_in[8];
    const float* Ur        = (const float*)d_in[9];
    const float* bur       = (const float*)d_in[10];
    const float* W         = (const float*)d_in[11];
    const float* bw        = (const float*)d_in[12];
    const float* U         = (const float*)d_in[13];
    const float* bu        = (const float*)d_in[14];
    const float* nm_w      = (const float*)d_in[15];
    const float* nm_b      = (const float*)d_in[16];
    float* out = (float*)d_out;

    const int scan_smem = 131072 + 16 * 16 * 33 * 8;   // wpk + red = 198656
    cudaFuncSetAttribute(scan_persist,
                         cudaFuncAttributeMaxDynamicSharedMemorySize, scan_smem);

    prep_kernel<<<128, 256>>>(Wr, W);
    gate_kernel<<<dim3(2, 4, BB), 256>>>(facts, questions, prevM, z1_w, z1_b, z2_w);
    softmax_kernel<<<BB, 256>>>();
    scan_persist<<<128, 512, scan_smem>>>(facts, Ur, U, br, bur, bw, bu);
    final_kernel<<<BB, 512>>>(prevM, questions, nm_w, nm_b, out);
}

// round 9
// speedup vs baseline: 1.4566x; 1.4566x over previous
#include <cuda_runtime.h>
#include <math.h>

#define BB 128
#define SS 256
#define HH 512

typedef unsigned long long u64;

// ---------------- device scratch (no allocations allowed) -------------------
__device__ float g_rsWr[HH];            // rowsum(Wr)
__device__ float g_rsW[HH];             // rowsum(W)
__device__ float g_part[4][BB * SS];    // per-jblock logit partials
__device__ float g_Gt[SS * BB];         // softmax gates, (s, b)
__device__ float g_C[2][HH * BB];       // recurrent state, transposed (h, b)
__device__ unsigned g_flags[8];         // per-bg step counters (zeroed by softmax)

// ---------------- f32x2 helpers ----------------------------------------------
__device__ __forceinline__ u64 pk2(float x, float y) {
    u64 r;
    asm("mov.b64 %0, {%1,%2};" : "=l"(r) : "f"(x), "f"(y));
    return r;
}
__device__ __forceinline__ void upk2(u64 v, float& x, float& y) {
    asm("mov.b64 {%0,%1}, %2;" : "=f"(x), "=f"(y) : "l"(v));
}
__device__ __forceinline__ u64 fma2_(u64 a, u64 b, u64 c) {
    u64 d;
    asm("fma.rn.f32x2 %0, %1, %2, %3;" : "=l"(d) : "l"(a), "l"(b), "l"(c));
    return d;
}
__device__ __forceinline__ u64 add2_(u64 a, u64 b) {
    u64 d;
    asm("add.rn.f32x2 %0, %1, %2;" : "=l"(d) : "l"(a), "l"(b));
    return d;
}
__device__ __forceinline__ float tanh_approx(float x) {
    float y;
    asm("tanh.approx.f32 %0, %1;" : "=f"(y) : "f"(x));
    return y;
}
__device__ __forceinline__ unsigned ld_acq(const unsigned* p) {
    unsigned v;
    asm volatile("ld.acquire.gpu.global.u32 %0, [%1];" : "=r"(v) : "l"(p));
    return v;
}

// ---------------- prep: rowsums of Wr and W ----------------------------------
__global__ void prep_kernel(const float* __restrict__ Wr, const float* __restrict__ W)
{
    int warp = threadIdx.x >> 5, lane = threadIdx.x & 31;
    int rowId = blockIdx.x * 8 + warp;               // 0..1023
    const float* src = (rowId < HH) ? Wr : W;
    int h = rowId & (HH - 1);
    const float4* s4 = reinterpret_cast<const float4*>(src + (size_t)h * HH);
    float s = 0.f;
    for (int i = lane; i < HH / 4; i += 32) {
        float4 v = s4[i];
        s += (v.x + v.y) + (v.z + v.w);
    }
#pragma unroll
    for (int o = 16; o > 0; o >>= 1) s += __shfl_xor_sync(0xffffffffu, s, o);
    if (lane == 0) {
        if (rowId < HH) g_rsWr[h] = s;
        else            g_rsW[h]  = s;
    }
}

// ---------------- gate MLP: fused z-build + GEMM (f32x2, 8x8) + tanh + dot ---
// grid (S/128, 512/128, B), 256 threads. 128x128 tile, K=2048 built on the fly.
// Bs double-buffered with register prefetch: 1 sync per B-tile.
__global__ void __launch_bounds__(256, 2) gate_kernel(
    const float* __restrict__ facts, const float* __restrict__ q,
    const float* __restrict__ m, const float* __restrict__ z1w,
    const float* __restrict__ z1b, const float* __restrict__ z2w)
{
    __shared__ float qs[HH], ms[HH];
    __shared__ float As[4][16][132];   // padded rows: kill STS conflicts
    __shared__ float Bs[2][16][128];   // double buffer

    int tid = threadIdx.x;
    int b  = blockIdx.z;
    int s0 = blockIdx.x * 128;
    int j0 = blockIdx.y * 128;

    for (int i = tid; i < HH; i += 256) {
        qs[i] = q[b * HH + i];
        ms[i] = m[b * HH + i];
    }

    const float* fb = facts + ((size_t)b * SS + s0) * HH;

    // A-build fixed sub-indices: element r -> (ss, kk) within a 128x16 k-tile
    int a_ss[8], a_kk[8];
#pragma unroll
    for (int r = 0; r < 8; r++) { int i = tid + r * 256; a_ss[r] = i >> 4; a_kk[r] = i & 15; }

    // facts prefetch for k-tile 0
    float freg[8];
#pragma unroll
    for (int r = 0; r < 8; r++) freg[r] = fb[(size_t)a_ss[r] * HH + a_kk[r]];

    // B prefetch: tile t -> z1w rows [ (t&3)*HH + (t>>2)*16 , +16 ), cols j0..+128
    float4 breg[2];
    {
        int kr = ((0 & 3) * HH) + ((0 >> 2) * 16);
#pragma unroll
        for (int r = 0; r < 2; r++) {
            int i = tid + r * 256; int kk = i >> 5, jj = (i & 31) * 4;
            breg[r] = *reinterpret_cast<const float4*>(
                &z1w[(size_t)(kr + kk) * HH + j0 + jj]);
        }
    }

    int tx = tid & 15, ty = tid >> 4;     // tx: 8 j's, ty: 8 s's
    u64 acc2[4][8];                        // [s-pair][j]
#pragma unroll
    for (int i = 0; i < 4; i++)
#pragma unroll
        for (int j = 0; j < 8; j++) acc2[i][j] = 0ull;

    __syncthreads();     // qs/ms visible for As builds
    // store B tile 0, prefetch tile 1
    {
#pragma unroll
        for (int r = 0; r < 2; r++) {
            int i = tid + r * 256; int kk = i >> 5, jj = (i & 31) * 4;
            *reinterpret_cast<float4*>(&Bs[0][kk][jj]) = breg[r];
        }
        int kr = ((1 & 3) * HH) + ((1 >> 2) * 16);
#pragma unroll
        for (int r = 0; r < 2; r++) {
            int i = tid + r * 256; int kk = i >> 5, jj = (i & 31) * 4;
            breg[r] = *reinterpret_cast<const float4*>(
                &z1w[(size_t)(kr + kk) * HH + j0 + jj]);
        }
    }

    for (int t = 0; t < 128; t++) {
        int blk = t & 3;
        __syncthreads();   // Bs[t&1] visible; compute t-1 done (As/other buf free)
        if (blk == 0) {
            int k0 = (t >> 2) * 16;
#pragma unroll
            for (int r = 0; r < 8; r++) {
                float fv = freg[r];
                int kk = k0 + a_kk[r];
                float qv = qs[kk], mv = ms[kk];
                As[0][a_kk[r]][a_ss[r]] = fv * qv;
                As[1][a_kk[r]][a_ss[r]] = fv * mv;
                As[2][a_kk[r]][a_ss[r]] = fabsf(fv - qv);
                As[3][a_kk[r]][a_ss[r]] = fabsf(fv - mv);
            }
            if (t + 4 < 128) {
                int k0n = k0 + 16;
#pragma unroll
                for (int r = 0; r < 8; r++)
                    freg[r] = fb[(size_t)a_ss[r] * HH + k0n + a_kk[r]];
            }
            __syncthreads();   // As ready
        }

        // compute tile t
        const float (*Bc)[128] = Bs[t & 1];
#pragma unroll
        for (int kk = 0; kk < 16; kk++) {
            ulonglong2 a01 = *reinterpret_cast<const ulonglong2*>(&As[blk][kk][ty * 8]);
            ulonglong2 a23 = *reinterpret_cast<const ulonglong2*>(&As[blk][kk][ty * 8 + 4]);
            float4 bv0 = *reinterpret_cast<const float4*>(&Bc[kk][tx * 8]);
            float4 bv1 = *reinterpret_cast<const float4*>(&Bc[kk][tx * 8 + 4]);
            u64 ap[4] = {a01.x, a01.y, a23.x, a23.y};
            float bf[8] = {bv0.x, bv0.y, bv0.z, bv0.w, bv1.x, bv1.y, bv1.z, bv1.w};
#pragma unroll
            for (int j = 0; j < 8; j++) {
                u64 bd = pk2(bf[j], bf[j]);
#pragma unroll
                for (int i = 0; i < 4; i++)
                    acc2[i][j] = fma2_(ap[i], bd, acc2[i][j]);
            }
        }

        // stage next tile: STS t+1 (other buffer), prefetch t+2
        if (t < 127) {
#pragma unroll
            for (int r = 0; r < 2; r++) {
                int i = tid + r * 256; int kk = i >> 5, jj = (i & 31) * 4;
                *reinterpret_cast<float4*>(&Bs[(t + 1) & 1][kk][jj]) = breg[r];
            }
            if (t < 126) {
                int tn = t + 2;
                int kr = ((tn & 3) * HH) + ((tn >> 2) * 16);
#pragma unroll
                for (int r = 0; r < 2; r++) {
                    int i = tid + r * 256; int kk = i >> 5, jj = (i & 31) * 4;
                    breg[r] = *reinterpret_cast<const float4*>(
                        &z1w[(size_t)(kr + kk) * HH + j0 + jj]);
                }
            }
        }
    }

    // epilogue: tanh (approx), dot with z2_w, reduce over the 128 j's
    float z1bv[8], z2wv[8];
#pragma unroll
    for (int j = 0; j < 8; j++) {
        int jc = j0 + tx * 8 + j;
        z1bv[j] = z1b[jc];
        z2wv[j] = z2w[jc];
    }
    float p[8];
#pragma unroll
    for (int i = 0; i < 8; i++) p[i] = 0.f;
#pragma unroll
    for (int ip = 0; ip < 4; ip++) {
#pragma unroll
        for (int j = 0; j < 8; j++) {
            float lo, hi;
            upk2(acc2[ip][j], lo, hi);
            p[ip * 2 + 0] = fmaf(tanh_approx(lo + z1bv[j]), z2wv[j], p[ip * 2 + 0]);
            p[ip * 2 + 1] = fmaf(tanh_approx(hi + z1bv[j]), z2wv[j], p[ip * 2 + 1]);
        }
    }
#pragma unroll
    for (int i = 0; i < 8; i++) {
#pragma unroll
        for (int o = 8; o > 0; o >>= 1)
            p[i] += __shfl_xor_sync(0xffffffffu, p[i], o);
    }
    if (tx == 0) {
#pragma unroll
        for (int i = 0; i < 8; i++)
            g_part[blockIdx.y][b * SS + s0 + ty * 8 + i] = p[i];
    }
}

// ---------------- softmax over S per batch (also zeroes scan flags) -----------
__global__ void softmax_kernel()
{
    int b = blockIdx.x, s = threadIdx.x;   // 256 threads
    if (b == 0 && s < 8) g_flags[s] = 0u;  // stream-ordered before scan launch
    float l = 0.f;
#pragma unroll
    for (int jb = 0; jb < 4; jb++) l += g_part[jb][b * SS + s];
    __shared__ float sm[256];
    sm[s] = l;
    __syncthreads();
#pragma unroll
    for (int o = 128; o > 0; o >>= 1) {
        if (s < o) sm[s] = fmaxf(sm[s], sm[s + o]);
        __syncthreads();
    }
    float mx = sm[0];
    __syncthreads();
    float e = expf(l - mx);
    sm[s] = e;
    __syncthreads();
#pragma unroll
    for (int o = 128; o > 0; o >>= 1) {
        if (s < o) sm[s] += sm[s + o];
        __syncthreads();
    }
    g_Gt[s * BB + b] = e / sm[0];
}

// ---------------- persistent scan: 128 blocks = 16 hg x 8 bg ------------------
// (R6 exact structure: measured 1.48 ms.) Block owns 32 h x 16 b. (R,U)-paired
// weights persist in smem (128KB). C read straight from L2. Per step: scalar
// flag poll -> FMA k-split GEMM -> 1 smem reduce -> fused epilogue.
__global__ void __launch_bounds__(512, 1) scan_persist(
    const float* __restrict__ facts,
    const float* __restrict__ Ur, const float* __restrict__ U,
    const float* __restrict__ br, const float* __restrict__ bur,
    const float* __restrict__ bw, const float* __restrict__ bu)
{
    extern __shared__ __align__(16) char dsm[];
    u64* wpk = reinterpret_cast<u64*>(dsm);            // [512][32]: pk2(Ur, U)
    u64* red = reinterpret_cast<u64*>(dsm + 131072);   // [16][16][33] padded

    __shared__ float hcs[5][32];

    int tid = threadIdx.x;
    int hg = blockIdx.x >> 3;      // 0..15
    int bg = blockIdx.x & 7;       // 0..7
    int h0 = hg * 32;
    int b0 = bg * 16;

    // one-time: pack (R,U) weight pairs for this h-slice
    for (int idx = tid; idx < 512 * 32; idx += 512) {
        int k = idx >> 5, h = idx & 31;
        wpk[idx] = pk2(Ur[(size_t)k * HH + h0 + h], U[(size_t)k * HH + h0 + h]);
    }
    if (tid < 32) {
        int h = h0 + tid;
        hcs[0][tid] = g_rsWr[h];
        hcs[1][tid] = br[h] + bur[h];
        hcs[2][tid] = g_rsW[h];
        hcs[3][tid] = bw[h];
        hcs[4][tid] = bu[h];
    }
    __syncthreads();

    // compute mapping
    int ks = tid >> 5;
    int lane = tid & 31;
    int hq = lane >> 2, bq = lane & 3;

    // reduce/epilogue mapping: one (h,b) per thread, fixed across steps
    int ep_pos = tid >> 4, ep_i = tid & 15;
    int e_hq = ep_pos >> 2, e_bq = ep_pos & 3;
    int e_hh = ep_i & 3,   e_bb = ep_i >> 2;        // hh fastest -> coalesced facts
    int ehl = e_hq * 4 + e_hh;                      // local h
    int eh  = h0 + ehl;
    int eb  = b0 + e_bq * 4 + e_bb;
    float cur_c = 0.f;

    for (int s = 0; s < SS; s++) {
        u64 aRU = 0ull;

        if (s > 0) {
            // scalar poll: all 16 producers of this bg finished step s-1
            unsigned target = 16u * (unsigned)s;
            while (ld_acq(&g_flags[bg]) < target) {}

            const float* __restrict__ Cin = g_C[s & 1];
            u64 acc[4][4];
#pragma unroll
            for (int i = 0; i < 4; i++)
#pragma unroll
                for (int j = 0; j < 4; j++) acc[i][j] = 0ull;

            const float4* cp = reinterpret_cast<const float4*>(
                Cin + (size_t)(ks * 32) * BB + b0 + bq * 4);
#pragma unroll 4
            for (int kk = 0; kk < 32; kk++) {
                float4 cv = __ldcg(cp + (size_t)kk * (BB / 4));
                u64 cd[4] = {pk2(cv.x, cv.x), pk2(cv.y, cv.y),
                             pk2(cv.z, cv.z), pk2(cv.w, cv.w)};
                const u64* wr = &wpk[(ks * 32 + kk) * 32 + hq * 4];
                ulonglong2 w01 = *reinterpret_cast<const ulonglong2*>(wr);
                ulonglong2 w23 = *reinterpret_cast<const ulonglong2*>(wr + 2);
                u64 w[4] = {w01.x, w01.y, w23.x, w23.y};
#pragma unroll
                for (int hh = 0; hh < 4; hh++)
#pragma unroll
                    for (int bb = 0; bb < 4; bb++)
                        acc[hh][bb] = fma2_(cd[bb], w[hh], acc[hh][bb]);
            }

            // write k-split partials (prev step's red reads sealed by last sync)
#pragma unroll
            for (int hh = 0; hh < 4; hh++)
#pragma unroll
                for (int bb = 0; bb < 4; bb++) {
                    int i = bb * 4 + hh;
                    red[(size_t)(ks * 16 + i) * 33 + lane] = acc[hh][bb];
                }
            __syncthreads();

            // each thread sums its 16 k-split partials for its own (h,b)
            u64 v = red[(size_t)ep_i * 33 + ep_pos];
#pragma unroll
            for (int t = 1; t < 16; t++)
                v = add2_(v, red[(size_t)(t * 16 + ep_i) * 33 + ep_pos]);
            aRU = v;
        }

        // fused epilogue: nonlinearity + blend; C kept in a register
        {
            float aR, aU;
            upk2(aRU, aR, aU);
            float* __restrict__ Cout = g_C[(s + 1) & 1];
            float fv = __ldg(facts + ((size_t)eb * SS + s) * HH + eh);
            float g = g_Gt[s * BB + eb];
            float rr = 1.f / (1.f + expf(-(fmaf(fv, hcs[0][ehl], hcs[1][ehl]) + aR)));
            float ht = tanhf(fmaf(rr, aU + hcs[4][ehl],
                                  fmaf(fv, hcs[2][ehl], hcs[3][ehl])));
            cur_c = fmaf(g, ht - cur_c, cur_c);
            Cout[(size_t)eh * BB + eb] = cur_c;
        }
        __threadfence();       // each thread makes its C store globally visible
        __syncthreads();       // all stores + fences done
        if (tid == 0) atomicAdd(&g_flags[bg], 1u);
    }
}

// ---------------- final: relu(concat @ nm_w + nm_b) ---------------------------
__global__ void __launch_bounds__(512) final_kernel(
    const float* __restrict__ prevM, const float* __restrict__ q,
    const float* __restrict__ nm_w, const float* __restrict__ nm_b,
    float* __restrict__ out)
{
    __shared__ float cs[3 * HH];
    int b = blockIdx.x, tid = threadIdx.x;    // 512 threads
    cs[tid]          = prevM[b * HH + tid];
    cs[HH + tid]     = g_C[0][(size_t)tid * BB + b];   // final C lives in buffer 0
    cs[2 * HH + tid] = q[b * HH + tid];
    __syncthreads();
    float acc = nm_b[tid];
#pragma unroll 8
    for (int k = 0; k < 3 * HH; k++)
        acc = fmaf(cs[k], nm_w[(size_t)k * HH + tid], acc);
    out[b * HH + tid] = fmaxf(acc, 0.f);
}

// ---------------- launch -------------------------------------------------------
extern "C" void kernel_launch(void* const* d_in, const int* in_sizes, int n_in,
                              void* d_out, int out_size)
{
    const float* facts     = (const float*)d_in[0];
    const float* questions = (const float*)d_in[1];
    const float* prevM     = (const float*)d_in[2];
    const float* z1_w      = (const float*)d_in[3];
    const float* z1_b      = (const float*)d_in[4];
    const float* z2_w      = (const float*)d_in[5];
    // d_in[6] z2_b: constant shift, softmax-invariant — unused
    const float* Wr        = (const float*)d_in[7];
    const float* br        = (const float*)d_in[8];
    const float* Ur        = (const float*)d_in[9];
    const float* bur       = (const float*)d_in[10];
    const float* W         = (const float*)d_in[11];
    const float* bw        = (const float*)d_in[12];
    const float* U         = (const float*)d_in[13];
    const float* bu        = (const float*)d_in[14];
    const float* nm_w      = (const float*)d_in[15];
    const float* nm_b      = (const float*)d_in[16];
    float* out = (float*)d_out;

    const int scan_smem = 131072 + 16 * 16 * 33 * 8;   // wpk + red = 198656
    cudaFuncSetAttribute(scan_persist,
                         cudaFuncAttributeMaxDynamicSharedMemorySize, scan_smem);

    prep_kernel<<<128, 256>>>(Wr, W);
    gate_kernel<<<dim3(2, 4, BB), 256>>>(facts, questions, prevM, z1_w, z1_b, z2_w);
    softmax_kernel<<<BB, 256>>>();
    scan_persist<<<128, 512, scan_smem>>>(facts, Ur, U, br, bur, bw, bu);
    final_kernel<<<BB, 512>>>(prevM, questions, nm_w, nm_b, out);
}

// round 10
// speedup vs baseline: 1.4825x; 1.0177x over previous
#include <cuda_runtime.h>
#include <math.h>

#define BB 128
#define SS 256
#define HH 512

typedef unsigned long long u64;

// ---------------- device scratch (no allocations allowed) -------------------
__device__ float g_rsWr[HH];            // rowsum(Wr)
__device__ float g_rsW[HH];             // rowsum(W)
__device__ float g_part[4][BB * SS];    // per-jblock logit partials
__device__ float g_Gt[SS * BB];         // softmax gates, (s, b)
__device__ float g_C[2][HH * BB];       // recurrent state, transposed (h, b)
__device__ unsigned g_flags[8][32];     // per-bg step counters, 128B padded

// ---------------- f32x2 helpers ----------------------------------------------
__device__ __forceinline__ u64 pk2(float x, float y) {
    u64 r;
    asm("mov.b64 %0, {%1,%2};" : "=l"(r) : "f"(x), "f"(y));
    return r;
}
__device__ __forceinline__ void upk2(u64 v, float& x, float& y) {
    asm("mov.b64 {%0,%1}, %2;" : "=f"(x), "=f"(y) : "l"(v));
}
__device__ __forceinline__ u64 fma2_(u64 a, u64 b, u64 c) {
    u64 d;
    asm("fma.rn.f32x2 %0, %1, %2, %3;" : "=l"(d) : "l"(a), "l"(b), "l"(c));
    return d;
}
__device__ __forceinline__ u64 add2_(u64 a, u64 b) {
    u64 d;
    asm("add.rn.f32x2 %0, %1, %2;" : "=l"(d) : "l"(a), "l"(b));
    return d;
}
__device__ __forceinline__ float tanh_approx(float x) {
    float y;
    asm("tanh.approx.f32 %0, %1;" : "=f"(y) : "f"(x));
    return y;
}
__device__ __forceinline__ unsigned ld_acq(const unsigned* p) {
    unsigned v;
    asm volatile("ld.acquire.gpu.global.u32 %0, [%1];" : "=r"(v) : "l"(p));
    return v;
}
__device__ __forceinline__ void red_add_rel(unsigned* p, unsigned v) {
    asm volatile("red.add.release.gpu.global.u32 [%0], %1;" :: "l"(p), "r"(v) : "memory");
}

// ---------------- prep: rowsums of Wr and W ----------------------------------
__global__ void prep_kernel(const float* __restrict__ Wr, const float* __restrict__ W)
{
    int warp = threadIdx.x >> 5, lane = threadIdx.x & 31;
    int rowId = blockIdx.x * 8 + warp;               // 0..1023
    const float* src = (rowId < HH) ? Wr : W;
    int h = rowId & (HH - 1);
    const float4* s4 = reinterpret_cast<const float4*>(src + (size_t)h * HH);
    float s = 0.f;
    for (int i = lane; i < HH / 4; i += 32) {
        float4 v = s4[i];
        s += (v.x + v.y) + (v.z + v.w);
    }
#pragma unroll
    for (int o = 16; o > 0; o >>= 1) s += __shfl_xor_sync(0xffffffffu, s, o);
    if (lane == 0) {
        if (rowId < HH) g_rsWr[h] = s;
        else            g_rsW[h]  = s;
    }
}

// ---------------- gate MLP: fused z-build + GEMM (f32x2, 8x8) + tanh + dot ---
// grid (S/128, 512/128, B), 256 threads. 128x128 tile, K=2048 built on the fly.
// Bs double-buffered with register prefetch: 1 sync per B-tile.
__global__ void __launch_bounds__(256, 2) gate_kernel(
    const float* __restrict__ facts, const float* __restrict__ q,
    const float* __restrict__ m, const float* __restrict__ z1w,
    const float* __restrict__ z1b, const float* __restrict__ z2w)
{
    __shared__ float qs[HH], ms[HH];
    __shared__ float As[4][16][132];   // padded rows: kill STS conflicts
    __shared__ float Bs[2][16][128];   // double buffer

    int tid = threadIdx.x;
    int b  = blockIdx.z;
    int s0 = blockIdx.x * 128;
    int j0 = blockIdx.y * 128;

    for (int i = tid; i < HH; i += 256) {
        qs[i] = q[b * HH + i];
        ms[i] = m[b * HH + i];
    }

    const float* fb = facts + ((size_t)b * SS + s0) * HH;

    // A-build fixed sub-indices: element r -> (ss, kk) within a 128x16 k-tile
    int a_ss[8], a_kk[8];
#pragma unroll
    for (int r = 0; r < 8; r++) { int i = tid + r * 256; a_ss[r] = i >> 4; a_kk[r] = i & 15; }

    // facts prefetch for k-tile 0
    float freg[8];
#pragma unroll
    for (int r = 0; r < 8; r++) freg[r] = fb[(size_t)a_ss[r] * HH + a_kk[r]];

    // B prefetch: tile t -> z1w rows [ (t&3)*HH + (t>>2)*16 , +16 ), cols j0..+128
    float4 breg[2];
    {
        int kr = ((0 & 3) * HH) + ((0 >> 2) * 16);
#pragma unroll
        for (int r = 0; r < 2; r++) {
            int i = tid + r * 256; int kk = i >> 5, jj = (i & 31) * 4;
            breg[r] = *reinterpret_cast<const float4*>(
                &z1w[(size_t)(kr + kk) * HH + j0 + jj]);
        }
    }

    int tx = tid & 15, ty = tid >> 4;     // tx: 8 j's, ty: 8 s's
    u64 acc2[4][8];                        // [s-pair][j]
#pragma unroll
    for (int i = 0; i < 4; i++)
#pragma unroll
        for (int j = 0; j < 8; j++) acc2[i][j] = 0ull;

    __syncthreads();     // qs/ms visible for As builds
    // store B tile 0, prefetch tile 1
    {
#pragma unroll
        for (int r = 0; r < 2; r++) {
            int i = tid + r * 256; int kk = i >> 5, jj = (i & 31) * 4;
            *reinterpret_cast<float4*>(&Bs[0][kk][jj]) = breg[r];
        }
        int kr = ((1 & 3) * HH) + ((1 >> 2) * 16);
#pragma unroll
        for (int r = 0; r < 2; r++) {
            int i = tid + r * 256; int kk = i >> 5, jj = (i & 31) * 4;
            breg[r] = *reinterpret_cast<const float4*>(
                &z1w[(size_t)(kr + kk) * HH + j0 + jj]);
        }
    }

    for (int t = 0; t < 128; t++) {
        int blk = t & 3;
        __syncthreads();   // Bs[t&1] visible; compute t-1 done (As/other buf free)
        if (blk == 0) {
            int k0 = (t >> 2) * 16;
#pragma unroll
            for (int r = 0; r < 8; r++) {
                float fv = freg[r];
                int kk = k0 + a_kk[r];
                float qv = qs[kk], mv = ms[kk];
                As[0][a_kk[r]][a_ss[r]] = fv * qv;
                As[1][a_kk[r]][a_ss[r]] = fv * mv;
                As[2][a_kk[r]][a_ss[r]] = fabsf(fv - qv);
                As[3][a_kk[r]][a_ss[r]] = fabsf(fv - mv);
            }
            if (t + 4 < 128) {
                int k0n = k0 + 16;
#pragma unroll
                for (int r = 0; r < 8; r++)
                    freg[r] = fb[(size_t)a_ss[r] * HH + k0n + a_kk[r]];
            }
            __syncthreads();   // As ready
        }

        // compute tile t
        const float (*Bc)[128] = Bs[t & 1];
#pragma unroll
        for (int kk = 0; kk < 16; kk++) {
            ulonglong2 a01 = *reinterpret_cast<const ulonglong2*>(&As[blk][kk][ty * 8]);
            ulonglong2 a23 = *reinterpret_cast<const ulonglong2*>(&As[blk][kk][ty * 8 + 4]);
            float4 bv0 = *reinterpret_cast<const float4*>(&Bc[kk][tx * 8]);
            float4 bv1 = *reinterpret_cast<const float4*>(&Bc[kk][tx * 8 + 4]);
            u64 ap[4] = {a01.x, a01.y, a23.x, a23.y};
            float bf[8] = {bv0.x, bv0.y, bv0.z, bv0.w, bv1.x, bv1.y, bv1.z, bv1.w};
#pragma unroll
            for (int j = 0; j < 8; j++) {
                u64 bd = pk2(bf[j], bf[j]);
#pragma unroll
                for (int i = 0; i < 4; i++)
                    acc2[i][j] = fma2_(ap[i], bd, acc2[i][j]);
            }
        }

        // stage next tile: STS t+1 (other buffer), prefetch t+2
        if (t < 127) {
#pragma unroll
            for (int r = 0; r < 2; r++) {
                int i = tid + r * 256; int kk = i >> 5, jj = (i & 31) * 4;
                *reinterpret_cast<float4*>(&Bs[(t + 1) & 1][kk][jj]) = breg[r];
            }
            if (t < 126) {
                int tn = t + 2;
                int kr = ((tn & 3) * HH) + ((tn >> 2) * 16);
#pragma unroll
                for (int r = 0; r < 2; r++) {
                    int i = tid + r * 256; int kk = i >> 5, jj = (i & 31) * 4;
                    breg[r] = *reinterpret_cast<const float4*>(
                        &z1w[(size_t)(kr + kk) * HH + j0 + jj]);
                }
            }
        }
    }

    // epilogue: tanh (approx), dot with z2_w, reduce over the 128 j's
    float z1bv[8], z2wv[8];
#pragma unroll
    for (int j = 0; j < 8; j++) {
        int jc = j0 + tx * 8 + j;
        z1bv[j] = z1b[jc];
        z2wv[j] = z2w[jc];
    }
    float p[8];
#pragma unroll
    for (int i = 0; i < 8; i++) p[i] = 0.f;
#pragma unroll
    for (int ip = 0; ip < 4; ip++) {
#pragma unroll
        for (int j = 0; j < 8; j++) {
            float lo, hi;
            upk2(acc2[ip][j], lo, hi);
            p[ip * 2 + 0] = fmaf(tanh_approx(lo + z1bv[j]), z2wv[j], p[ip * 2 + 0]);
            p[ip * 2 + 1] = fmaf(tanh_approx(hi + z1bv[j]), z2wv[j], p[ip * 2 + 1]);
        }
    }
#pragma unroll
    for (int i = 0; i < 8; i++) {
#pragma unroll
        for (int o = 8; o > 0; o >>= 1)
            p[i] += __shfl_xor_sync(0xffffffffu, p[i], o);
    }
    if (tx == 0) {
#pragma unroll
        for (int i = 0; i < 8; i++)
            g_part[blockIdx.y][b * SS + s0 + ty * 8 + i] = p[i];
    }
}

// ---------------- softmax over S per batch (also zeroes scan flags) -----------
__global__ void softmax_kernel()
{
    int b = blockIdx.x, s = threadIdx.x;   // 256 threads
    if (b == 0) g_flags[s >> 5][s & 31] = 0u;  // zero all padded flag words
    float l = 0.f;
#pragma unroll
    for (int jb = 0; jb < 4; jb++) l += g_part[jb][b * SS + s];
    __shared__ float sm[256];
    sm[s] = l;
    __syncthreads();
#pragma unroll
    for (int o = 128; o > 0; o >>= 1) {
        if (s < o) sm[s] = fmaxf(sm[s], sm[s + o]);
        __syncthreads();
    }
    float mx = sm[0];
    __syncthreads();
    float e = expf(l - mx);
    sm[s] = e;
    __syncthreads();
#pragma unroll
    for (int o = 128; o > 0; o >>= 1) {
        if (s < o) sm[s] += sm[s + o];
        __syncthreads();
    }
    g_Gt[s * BB + b] = e / sm[0];
}

// ---------------- persistent scan: 128 blocks = 16 hg x 8 bg ------------------
// Block owns 32 h x 16 b. (R,U)-paired weights persist in smem (128KB).
// C read straight from L2. Per step: lane0-acquire poll -> FMA k-split GEMM
// -> 1 smem reduce -> fused epilogue -> syncthreads -> tid0 release-add.
__global__ void __launch_bounds__(512, 1) scan_persist(
    const float* __restrict__ facts,
    const float* __restrict__ Ur, const float* __restrict__ U,
    const float* __restrict__ br, const float* __restrict__ bur,
    const float* __restrict__ bw, const float* __restrict__ bu)
{
    extern __shared__ __align__(16) char dsm[];
    u64* wpk = reinterpret_cast<u64*>(dsm);            // [512][32]: pk2(Ur, U)
    u64* red = reinterpret_cast<u64*>(dsm + 131072);   // [16][16][33] padded

    __shared__ float hcs[5][32];

    int tid = threadIdx.x;
    int hg = blockIdx.x >> 3;      // 0..15
    int bg = blockIdx.x & 7;       // 0..7
    int h0 = hg * 32;
    int b0 = bg * 16;

    // one-time: pack (R,U) weight pairs for this h-slice
    for (int idx = tid; idx < 512 * 32; idx += 512) {
        int k = idx >> 5, h = idx & 31;
        wpk[idx] = pk2(Ur[(size_t)k * HH + h0 + h], U[(size_t)k * HH + h0 + h]);
    }
    if (tid < 32) {
        int h = h0 + tid;
        hcs[0][tid] = g_rsWr[h];
        hcs[1][tid] = br[h] + bur[h];
        hcs[2][tid] = g_rsW[h];
        hcs[3][tid] = bw[h];
        hcs[4][tid] = bu[h];
    }
    __syncthreads();

    // compute mapping
    int ks = tid >> 5;
    int lane = tid & 31;
    int hq = lane >> 2, bq = lane & 3;

    // reduce/epilogue mapping: one (h,b) per thread, fixed across steps
    int ep_pos = tid >> 4, ep_i = tid & 15;
    int e_hq = ep_pos >> 2, e_bq = ep_pos & 3;
    int e_hh = ep_i & 3,   e_bb = ep_i >> 2;        // hh fastest -> coalesced facts
    int ehl = e_hq * 4 + e_hh;                      // local h
    int eh  = h0 + ehl;
    int eb  = b0 + e_bq * 4 + e_bb;
    float cur_c = 0.f;

    for (int s = 0; s < SS; s++) {
        u64 aRU = 0ull;

        if (s > 0) {
            // lane0-acquire poll: all 16 producers of this bg finished step s-1
            unsigned target = 16u * (unsigned)s;
            if (lane == 0) {
                while (ld_acq(&g_flags[bg][0]) < target) {}
            }
            __syncwarp();   // extend lane0's acquire to the whole warp

            const float* __restrict__ Cin = g_C[s & 1];
            u64 acc[4][4];
#pragma unroll
            for (int i = 0; i < 4; i++)
#pragma unroll
                for (int j = 0; j < 4; j++) acc[i][j] = 0ull;

            const float4* cp = reinterpret_cast<const float4*>(
                Cin + (size_t)(ks * 32) * BB + b0 + bq * 4);
#pragma unroll 4
            for (int kk = 0; kk < 32; kk++) {
                float4 cv = __ldcg(cp + (size_t)kk * (BB / 4));
                u64 cd[4] = {pk2(cv.x, cv.x), pk2(cv.y, cv.y),
                             pk2(cv.z, cv.z), pk2(cv.w, cv.w)};
                const u64* wr = &wpk[(ks * 32 + kk) * 32 + hq * 4];
                ulonglong2 w01 = *reinterpret_cast<const ulonglong2*>(wr);
                ulonglong2 w23 = *reinterpret_cast<const ulonglong2*>(wr + 2);
                u64 w[4] = {w01.x, w01.y, w23.x, w23.y};
#pragma unroll
                for (int hh = 0; hh < 4; hh++)
#pragma unroll
                    for (int bb = 0; bb < 4; bb++)
                        acc[hh][bb] = fma2_(cd[bb], w[hh], acc[hh][bb]);
            }

            // write k-split partials (prev step's red reads sealed by last sync)
#pragma unroll
            for (int hh = 0; hh < 4; hh++)
#pragma unroll
                for (int bb = 0; bb < 4; bb++) {
                    int i = bb * 4 + hh;
                    red[(size_t)(ks * 16 + i) * 33 + lane] = acc[hh][bb];
                }
            __syncthreads();

            // each thread sums its 16 k-split partials for its own (h,b)
            u64 v = red[(size_t)ep_i * 33 + ep_pos];
#pragma unroll
            for (int t = 1; t < 16; t++)
                v = add2_(v, red[(size_t)(t * 16 + ep_i) * 33 + ep_pos]);
            aRU = v;
        }

        // fused epilogue: nonlinearity + blend; C kept in a register
        {
            float aR, aU;
            upk2(aRU, aR, aU);
            float* __restrict__ Cout = g_C[(s + 1) & 1];
            float fv = __ldg(facts + ((size_t)eb * SS + s) * HH + eh);
            float g = g_Gt[s * BB + eb];
            float rr = 1.f / (1.f + expf(-(fmaf(fv, hcs[0][ehl], hcs[1][ehl]) + aR)));
            float ht = tanhf(fmaf(rr, aU + hcs[4][ehl],
                                  fmaf(fv, hcs[2][ehl], hcs[3][ehl])));
            cur_c = fmaf(g, ht - cur_c, cur_c);
            __stcg(&Cout[(size_t)eh * BB + eb], cur_c);
        }
        __syncthreads();       // all C stores in this block issued (program order)
        // release-add: orders this block's stores (via syncthreads hb) before
        // the flag increment that consumers acquire.
        if (tid == 0) red_add_rel(&g_flags[bg][0], 1u);
    }
}

// ---------------- final: relu(concat @ nm_w + nm_b) ---------------------------
__global__ void __launch_bounds__(512) final_kernel(
    const float* __restrict__ prevM, const float* __restrict__ q,
    const float* __restrict__ nm_w, const float* __restrict__ nm_b,
    float* __restrict__ out)
{
    __shared__ float cs[3 * HH];
    int b = blockIdx.x, tid = threadIdx.x;    // 512 threads
    cs[tid]          = prevM[b * HH + tid];
    cs[HH + tid]     = g_C[0][(size_t)tid * BB + b];   // final C lives in buffer 0
    cs[2 * HH + tid] = q[b * HH + tid];
    __syncthreads();
    float acc = nm_b[tid];
#pragma unroll 8
    for (int k = 0; k < 3 * HH; k++)
        acc = fmaf(cs[k], nm_w[(size_t)k * HH + tid], acc);
    out[b * HH + tid] = fmaxf(acc, 0.f);
}

// ---------------- launch -------------------------------------------------------
extern "C" void kernel_launch(void* const* d_in, const int* in_sizes, int n_in,
                              void* d_out, int out_size)
{
    const float* facts     = (const float*)d_in[0];
    const float* questions = (const float*)d_in[1];
    const float* prevM     = (const float*)d_in[2];
    const float* z1_w      = (const float*)d_in[3];
    const float* z1_b      = (const float*)d_in[4];
    const float* z2_w      = (const float*)d_in[5];
    // d_in[6] z2_b: constant shift, softmax-invariant — unused
    const float* Wr        = (const float*)d_in[7];
    const float* br        = (const float*)d_in[8];
    const float* Ur        = (const float*)d_in[9];
    const float* bur       = (const float*)d_in[10];
    const float* W         = (const float*)d_in[11];
    const float* bw        = (const float*)d_in[12];
    const float* U         = (const float*)d_in[13];
    const float* bu        = (const float*)d_in[14];
    const float* nm_w      = (const float*)d_in[15];
    const float* nm_b      = (const float*)d_in[16];
    float* out = (float*)d_out;

    const int scan_smem = 131072 + 16 * 16 * 33 * 8;   // wpk + red = 198656
    cudaFuncSetAttribute(scan_persist,
                         cudaFuncAttributeMaxDynamicSharedMemorySize, scan_smem);

    prep_kernel<<<128, 256>>>(Wr, W);
    gate_kernel<<<dim3(2, 4, BB), 256>>>(facts, questions, prevM, z1_w, z1_b, z2_w);
    softmax_kernel<<<BB, 256>>>();
    scan_persist<<<128, 512, scan_smem>>>(facts, Ur, U, br, bur, bw, bu);
    final_kernel<<<BB, 512>>>(prevM, questions, nm_w, nm_b, out);
}

// round 11
// speedup vs baseline: 2.0643x; 1.3924x over previous
#include <cuda_runtime.h>
#include <math.h>

#define BB 128
#define SS 256
#define HH 512

typedef unsigned long long u64;

// ---------------- device scratch (no allocations allowed) -------------------
__device__ float g_rsWr[HH];            // rowsum(Wr)
__device__ float g_rsW[HH];             // rowsum(W)
__device__ float g_part[4][BB * SS];    // per-jblock logit partials
__device__ float g_Gt[SS * BB];         // softmax gates, (s, b)
__device__ float g_C[2][HH * BB];       // recurrent state, transposed (h, b)
__device__ unsigned g_flags[8][32];     // per-bg step counters, 128B padded

// ---------------- f32x2 / misc helpers ----------------------------------------
__device__ __forceinline__ u64 pk2(float x, float y) {
    u64 r;
    asm("mov.b64 %0, {%1,%2};" : "=l"(r) : "f"(x), "f"(y));
    return r;
}
__device__ __forceinline__ void upk2(u64 v, float& x, float& y) {
    asm("mov.b64 {%0,%1}, %2;" : "=f"(x), "=f"(y) : "l"(v));
}
__device__ __forceinline__ u64 fma2_(u64 a, u64 b, u64 c) {
    u64 d;
    asm("fma.rn.f32x2 %0, %1, %2, %3;" : "=l"(d) : "l"(a), "l"(b), "l"(c));
    return d;
}
__device__ __forceinline__ u64 add2_(u64 a, u64 b) {
    u64 d;
    asm("add.rn.f32x2 %0, %1, %2;" : "=l"(d) : "l"(a), "l"(b));
    return d;
}
__device__ __forceinline__ float tanh_approx(float x) {
    float y;
    asm("tanh.approx.f32 %0, %1;" : "=f"(y) : "f"(x));
    return y;
}
__device__ __forceinline__ float to_tf32(float x) {
    float y;
    asm("cvt.rna.tf32.f32 %0, %1;" : "=f"(y) : "f"(x));
    return y;
}
__device__ __forceinline__ unsigned ld_acq(const unsigned* p) {
    unsigned v;
    asm volatile("ld.acquire.gpu.global.u32 %0, [%1];" : "=r"(v) : "l"(p));
    return v;
}
__device__ __forceinline__ void red_add_rel(unsigned* p, unsigned v) {
    asm volatile("red.add.release.gpu.global.u32 [%0], %1;" :: "l"(p), "r"(v) : "memory");
}
__device__ __forceinline__ void mma_tf32(float* d, const unsigned* a,
                                         unsigned b0, unsigned b1) {
    asm volatile(
        "mma.sync.aligned.m16n8k8.row.col.f32.tf32.tf32.f32 "
        "{%0,%1,%2,%3}, {%4,%5,%6,%7}, {%8,%9}, {%0,%1,%2,%3};"
        : "+f"(d[0]), "+f"(d[1]), "+f"(d[2]), "+f"(d[3])
        : "r"(a[0]), "r"(a[1]), "r"(a[2]), "r"(a[3]), "r"(b0), "r"(b1));
}

// ---------------- prep: rowsums of Wr and W ----------------------------------
__global__ void prep_kernel(const float* __restrict__ Wr, const float* __restrict__ W)
{
    int warp = threadIdx.x >> 5, lane = threadIdx.x & 31;
    int rowId = blockIdx.x * 8 + warp;               // 0..1023
    const float* src = (rowId < HH) ? Wr : W;
    int h = rowId & (HH - 1);
    const float4* s4 = reinterpret_cast<const float4*>(src + (size_t)h * HH);
    float s = 0.f;
    for (int i = lane; i < HH / 4; i += 32) {
        float4 v = s4[i];
        s += (v.x + v.y) + (v.z + v.w);
    }
#pragma unroll
    for (int o = 16; o > 0; o >>= 1) s += __shfl_xor_sync(0xffffffffu, s, o);
    if (lane == 0) {
        if (rowId < HH) g_rsWr[h] = s;
        else            g_rsW[h]  = s;
    }
}

// ---------------- gate MLP: tf32 mma.sync + fused z-build + tanh + z2 dot -----
// grid (S/128, 512/128, B), 256 threads = 8 warps (4 s x 2 j).
// Block tile 128s x 128j, K=2048 built on the fly as tf32 in smem.
// Warp tile 32s x 64j = 2 x 8 m16n8k8 mma tiles.
__global__ void __launch_bounds__(256, 2) gate_kernel(
    const float* __restrict__ facts, const float* __restrict__ q,
    const float* __restrict__ m, const float* __restrict__ z1w,
    const float* __restrict__ z1b, const float* __restrict__ z2w)
{
    extern __shared__ __align__(16) float gsm[];
    float* As   = gsm;                   // [4][16][132] tf32 z-variants (k-major)
    float* Bs   = As + 4 * 16 * 132;     // [4][16][132] tf32 z1w tile (k-major)
    float* qs   = Bs + 4 * 16 * 132;     // [512]
    float* ms   = qs + HH;               // [512]
    float* z1bs = ms + HH;               // [128]
    float* z2ws = z1bs + 128;            // [128]
    float* ps   = z2ws + 128;            // [8][32] per-warp s-partials

    int tid = threadIdx.x;
    int b  = blockIdx.z;
    int s0 = blockIdx.x * 128;
    int j0 = blockIdx.y * 128;
    int wid = tid >> 5, lane = tid & 31;
    int ws = wid >> 1, wj = wid & 1;      // warp grid 4(s) x 2(j)
    int gp = lane >> 2, tg = lane & 3;    // mma group / thread-in-group

    for (int i = tid; i < HH; i += 256) {
        qs[i] = q[b * HH + i];
        ms[i] = m[b * HH + i];
    }
    if (tid < 128) {
        z1bs[tid] = z1b[j0 + tid];
        z2ws[tid] = z2w[j0 + tid];
    }

    const float* fb = facts + ((size_t)b * SS + s0) * HH;

    float acc[2][8][4];                   // [s-subtile][j-subtile][frag]
#pragma unroll
    for (int i = 0; i < 2; i++)
#pragma unroll
        for (int j = 0; j < 8; j++)
#pragma unroll
            for (int k = 0; k < 4; k++) acc[i][j][k] = 0.f;

    for (int c = 0; c < 32; c++) {        // 32 chunks of 16 facts-k
        int k0 = c * 16;
        __syncthreads();                  // prev compute done (covers qs/ms @c=0)

        // build As: 4 tf32 z-variants of the facts k-chunk
#pragma unroll
        for (int r = 0; r < 8; r++) {
            int idx = tid + r * 256;
            int ss = idx >> 4, kk = idx & 15;
            float fv = fb[(size_t)ss * HH + k0 + kk];
            float qv = qs[k0 + kk], mv = ms[k0 + kk];
            As[(0 * 16 + kk) * 132 + ss] = to_tf32(fv * qv);
            As[(1 * 16 + kk) * 132 + ss] = to_tf32(fv * mv);
            As[(2 * 16 + kk) * 132 + ss] = to_tf32(fabsf(fv - qv));
            As[(3 * 16 + kk) * 132 + ss] = to_tf32(fabsf(fv - mv));
        }
        // stage Bs: z1w rows {v*512 + k0 + kk}, cols j0..j0+127, as tf32
#pragma unroll
        for (int r = 0; r < 8; r++) {
            int idx = tid + r * 256;        // float4 index 0..2047
            int row = idx >> 5;             // 0..63: v = row>>4, kk = row&15
            int c4 = idx & 31;
            float4 v4 = *reinterpret_cast<const float4*>(
                &z1w[(size_t)((row >> 4) * HH + k0 + (row & 15)) * HH + j0 + c4 * 4]);
            float* dst = &Bs[row * 132 + c4 * 4];
            dst[0] = to_tf32(v4.x); dst[1] = to_tf32(v4.y);
            dst[2] = to_tf32(v4.z); dst[3] = to_tf32(v4.w);
        }
        __syncthreads();                  // As/Bs ready

        // compute: 4 variants x 2 k8-substeps
#pragma unroll
        for (int sub = 0; sub < 8; sub++) {
            int v = sub >> 1, k8 = (sub & 1) * 8;
            const float* Av = &As[v * 16 * 132];
            const float* Bv = &Bs[v * 16 * 132];
            unsigned a[2][4];
#pragma unroll
            for (int st = 0; st < 2; st++) {
                int row0 = ws * 32 + st * 16 + gp;
                a[st][0] = __float_as_uint(Av[(k8 + tg) * 132 + row0]);
                a[st][1] = __float_as_uint(Av[(k8 + tg) * 132 + row0 + 8]);
                a[st][2] = __float_as_uint(Av[(k8 + tg + 4) * 132 + row0]);
                a[st][3] = __float_as_uint(Av[(k8 + tg + 4) * 132 + row0 + 8]);
            }
#pragma unroll
            for (int jt = 0; jt < 8; jt++) {
                int n0 = wj * 64 + jt * 8 + gp;
                unsigned b0 = __float_as_uint(Bv[(k8 + tg) * 132 + n0]);
                unsigned b1 = __float_as_uint(Bv[(k8 + tg + 4) * 132 + n0]);
                mma_tf32(acc[0][jt], a[0], b0, b1);
                mma_tf32(acc[1][jt], a[1], b0, b1);
            }
        }
    }

    // epilogue: tanh(acc + z1b) . z2w, reduce over this block's 128 j
#pragma unroll
    for (int st = 0; st < 2; st++) {
        float s_r0 = 0.f, s_r1 = 0.f;
#pragma unroll
        for (int jt = 0; jt < 8; jt++) {
#pragma unroll
            for (int ci = 0; ci < 2; ci++) {
                int col = wj * 64 + jt * 8 + tg * 2 + ci;
                float zb = z1bs[col], zw = z2ws[col];
                s_r0 = fmaf(tanh_approx(acc[st][jt][ci] + zb), zw, s_r0);
                s_r1 = fmaf(tanh_approx(acc[st][jt][2 + ci] + zb), zw, s_r1);
            }
        }
        // reduce over the 4 lanes (tg) sharing each s-row
#pragma unroll
        for (int o = 1; o <= 2; o <<= 1) {
            s_r0 += __shfl_xor_sync(0xffffffffu, s_r0, o);
            s_r1 += __shfl_xor_sync(0xffffffffu, s_r1, o);
        }
        if (tg == 0) {
            ps[wid * 32 + st * 16 + gp]     = s_r0;
            ps[wid * 32 + st * 16 + 8 + gp] = s_r1;
        }
    }
    __syncthreads();
    if (tid < 128) {
        int wsx = tid >> 5, wi = tid & 31;
        float v = ps[(wsx * 2 + 0) * 32 + wi] + ps[(wsx * 2 + 1) * 32 + wi];
        g_part[blockIdx.y][b * SS + s0 + tid] = v;
    }
}

// ---------------- softmax over S per batch (also zeroes scan flags) -----------
__global__ void softmax_kernel()
{
    int b = blockIdx.x, s = threadIdx.x;   // 256 threads
    if (b == 0) g_flags[s >> 5][s & 31] = 0u;  // zero all padded flag words
    float l = 0.f;
#pragma unroll
    for (int jb = 0; jb < 4; jb++) l += g_part[jb][b * SS + s];
    __shared__ float sm[256];
    sm[s] = l;
    __syncthreads();
#pragma unroll
    for (int o = 128; o > 0; o >>= 1) {
        if (s < o) sm[s] = fmaxf(sm[s], sm[s + o]);
        __syncthreads();
    }
    float mx = sm[0];
    __syncthreads();
    float e = expf(l - mx);
    sm[s] = e;
    __syncthreads();
#pragma unroll
    for (int o = 128; o > 0; o >>= 1) {
        if (s < o) sm[s] += sm[s + o];
        __syncthreads();
    }
    g_Gt[s * BB + b] = e / sm[0];
}

// ---------------- persistent scan: 128 blocks = 16 hg x 8 bg ------------------
// Block owns 32 h x 16 b. (R,U)-paired weights persist in smem (128KB).
// C read straight from L2. Per step: lane0-acquire poll -> FMA k-split GEMM
// -> 1 smem reduce -> fused epilogue -> syncthreads -> tid0 release-add.
__global__ void __launch_bounds__(512, 1) scan_persist(
    const float* __restrict__ facts,
    const float* __restrict__ Ur, const float* __restrict__ U,
    const float* __restrict__ br, const float* __restrict__ bur,
    const float* __restrict__ bw, const float* __restrict__ bu)
{
    extern __shared__ __align__(16) char dsm[];
    u64* wpk = reinterpret_cast<u64*>(dsm);            // [512][32]: pk2(Ur, U)
    u64* red = reinterpret_cast<u64*>(dsm + 131072);   // [16][16][33] padded

    __shared__ float hcs[5][32];

    int tid = threadIdx.x;
    int hg = blockIdx.x >> 3;      // 0..15
    int bg = blockIdx.x & 7;       // 0..7
    int h0 = hg * 32;
    int b0 = bg * 16;

    // one-time: pack (R,U) weight pairs for this h-slice
    for (int idx = tid; idx < 512 * 32; idx += 512) {
        int k = idx >> 5, h = idx & 31;
        wpk[idx] = pk2(Ur[(size_t)k * HH + h0 + h], U[(size_t)k * HH + h0 + h]);
    }
    if (tid < 32) {
        int h = h0 + tid;
        hcs[0][tid] = g_rsWr[h];
        hcs[1][tid] = br[h] + bur[h];
        hcs[2][tid] = g_rsW[h];
        hcs[3][tid] = bw[h];
        hcs[4][tid] = bu[h];
    }
    __syncthreads();

    // compute mapping
    int ks = tid >> 5;
    int lane = tid & 31;
    int hq = lane >> 2, bq = lane & 3;

    // reduce/epilogue mapping: one (h,b) per thread, fixed across steps
    int ep_pos = tid >> 4, ep_i = tid & 15;
    int e_hq = ep_pos >> 2, e_bq = ep_pos & 3;
    int e_hh = ep_i & 3,   e_bb = ep_i >> 2;        // hh fastest -> coalesced facts
    int ehl = e_hq * 4 + e_hh;                      // local h
    int eh  = h0 + ehl;
    int eb  = b0 + e_bq * 4 + e_bb;
    float cur_c = 0.f;

    for (int s = 0; s < SS; s++) {
        u64 aRU = 0ull;

        if (s > 0) {
            // lane0-acquire poll: all 16 producers of this bg finished step s-1
            unsigned target = 16u * (unsigned)s;
            if (lane == 0) {
                while (ld_acq(&g_flags[bg][0]) < target) {}
            }
            __syncwarp();   // extend lane0's acquire to the whole warp

            const float* __restrict__ Cin = g_C[s & 1];
            u64 acc[4][4];
#pragma unroll
            for (int i = 0; i < 4; i++)
#pragma unroll
                for (int j = 0; j < 4; j++) acc[i][j] = 0ull;

            const float4* cp = reinterpret_cast<const float4*>(
                Cin + (size_t)(ks * 32) * BB + b0 + bq * 4);
#pragma unroll 4
            for (int kk = 0; kk < 32; kk++) {
                float4 cv = __ldcg(cp + (size_t)kk * (BB / 4));
                u64 cd[4] = {pk2(cv.x, cv.x), pk2(cv.y, cv.y),
                             pk2(cv.z, cv.z), pk2(cv.w, cv.w)};
                const u64* wr = &wpk[(ks * 32 + kk) * 32 + hq * 4];
                ulonglong2 w01 = *reinterpret_cast<const ulonglong2*>(wr);
                ulonglong2 w23 = *reinterpret_cast<const ulonglong2*>(wr + 2);
                u64 w[4] = {w01.x, w01.y, w23.x, w23.y};
#pragma unroll
                for (int hh = 0; hh < 4; hh++)
#pragma unroll
                    for (int bb = 0; bb < 4; bb++)
                        acc[hh][bb] = fma2_(cd[bb], w[hh], acc[hh][bb]);
            }

            // write k-split partials (prev step's red reads sealed by last sync)
#pragma unroll
            for (int hh = 0; hh < 4; hh++)
#pragma unroll
                for (int bb = 0; bb < 4; bb++) {
                    int i = bb * 4 + hh;
                    red[(size_t)(ks * 16 + i) * 33 + lane] = acc[hh][bb];
                }
            __syncthreads();

            // each thread sums its 16 k-split partials for its own (h,b)
            u64 v = red[(size_t)ep_i * 33 + ep_pos];
#pragma unroll
            for (int t = 1; t < 16; t++)
                v = add2_(v, red[(size_t)(t * 16 + ep_i) * 33 + ep_pos]);
            aRU = v;
        }

        // fused epilogue: nonlinearity + blend; C kept in a register
        {
            float aR, aU;
            upk2(aRU, aR, aU);
            float* __restrict__ Cout = g_C[(s + 1) & 1];
            float fv = __ldg(facts + ((size_t)eb * SS + s) * HH + eh);
            float g = g_Gt[s * BB + eb];
            float rr = 1.f / (1.f + expf(-(fmaf(fv, hcs[0][ehl], hcs[1][ehl]) + aR)));
            float ht = tanhf(fmaf(rr, aU + hcs[4][ehl],
                                  fmaf(fv, hcs[2][ehl], hcs[3][ehl])));
            cur_c = fmaf(g, ht - cur_c, cur_c);
            __stcg(&Cout[(size_t)eh * BB + eb], cur_c);
        }
        __syncthreads();       // all C stores in this block issued (program order)
        if (tid == 0) red_add_rel(&g_flags[bg][0], 1u);
    }
}

// ---------------- final: relu(concat @ nm_w + nm_b) ---------------------------
__global__ void __launch_bounds__(512) final_kernel(
    const float* __restrict__ prevM, const float* __restrict__ q,
    const float* __restrict__ nm_w, const float* __restrict__ nm_b,
    float* __restrict__ out)
{
    __shared__ float cs[3 * HH];
    int b = blockIdx.x, tid = threadIdx.x;    // 512 threads
    cs[tid]          = prevM[b * HH + tid];
    cs[HH + tid]     = g_C[0][(size_t)tid * BB + b];   // final C lives in buffer 0
    cs[2 * HH + tid] = q[b * HH + tid];
    __syncthreads();
    float acc = nm_b[tid];
#pragma unroll 8
    for (int k = 0; k < 3 * HH; k++)
        acc = fmaf(cs[k], nm_w[(size_t)k * HH + tid], acc);
    out[b * HH + tid] = fmaxf(acc, 0.f);
}

// ---------------- launch -------------------------------------------------------
extern "C" void kernel_launch(void* const* d_in, const int* in_sizes, int n_in,
                              void* d_out, int out_size)
{
    const float* facts     = (const float*)d_in[0];
    const float* questions = (const float*)d_in[1];
    const float* prevM     = (const float*)d_in[2];
    const float* z1_w      = (const float*)d_in[3];
    const float* z1_b      = (const float*)d_in[4];
    const float* z2_w      = (const float*)d_in[5];
    // d_in[6] z2_b: constant shift, softmax-invariant — unused
    const float* Wr        = (const float*)d_in[7];
    const float* br        = (const float*)d_in[8];
    const float* Ur        = (const float*)d_in[9];
    const float* bur       = (const float*)d_in[10];
    const float* W         = (const float*)d_in[11];
    const float* bw        = (const float*)d_in[12];
    const float* U         = (const float*)d_in[13];
    const float* bu        = (const float*)d_in[14];
    const float* nm_w      = (const float*)d_in[15];
    const float* nm_b      = (const float*)d_in[16];
    float* out = (float*)d_out;

    const int scan_smem = 131072 + 16 * 16 * 33 * 8;   // wpk + red = 198656
    cudaFuncSetAttribute(scan_persist,
                         cudaFuncAttributeMaxDynamicSharedMemorySize, scan_smem);
    const int gate_smem = (2 * 4 * 16 * 132 + 2 * HH + 2 * 128 + 256) * 4; // 73728
    cudaFuncSetAttribute(gate_kernel,
                         cudaFuncAttributeMaxDynamicSharedMemorySize, gate_smem);

    prep_kernel<<<128, 256>>>(Wr, W);
    gate_kernel<<<dim3(2, 4, BB), 256, gate_smem>>>(facts, questions, prevM,
                                                    z1_w, z1_b, z2_w);
    softmax_kernel<<<BB, 256>>>();
    scan_persist<<<128, 512, scan_smem>>>(facts, Ur, U, br, bur, bw, bu);
    final_kernel<<<BB, 512>>>(prevM, questions, nm_w, nm_b, out);
}